// round 4
// baseline (speedup 1.0000x reference)
#include <cuda_runtime.h>

// GAE: advantages/targets, B=4096 rows, T=8192 timesteps.
// delta_t = r_t + GAMMA * v_{t+1} - v_t
// A_t = delta_t + COEF * A_{t+1}   (reverse scan, COEF = GAMMA*LAMBDA)
// targets_t = v_t + A_t
// Output layout: [advantages (B*T) | targets (B*T)] float32.
//
// R4: single coalesced read of values (v[t+1] via warp shuffle), vt cached in
// smem so phase 5 does NO global reads; float4 stores; shuffle-based scan.
// 66KB smem -> 3 CTAs/SM (48 warps).

constexpr int   B_CONST  = 4096;
constexpr int   T_CONST  = 8192;
constexpr float GAMMA    = 0.99f;
constexpr float COEF     = 0.99f * 0.95f;           // gamma * lambda
constexpr int   THREADS  = 512;
constexpr int   NWARP    = THREADS / 32;            // 16
constexpr int   SEG      = T_CONST / THREADS;       // 16 elements per thread
constexpr int   NITER    = T_CONST / THREADS;       // 16 coalesced iters
constexpr int   TPAD     = T_CONST + T_CONST / 32;  // 8448: +1 pad per 32

__device__ __forceinline__ int padi(int t) { return t + (t >> 5); }

__global__ __launch_bounds__(THREADS, 3)
void gae_kernel(const float* __restrict__ rewards,
                const float* __restrict__ values,
                float* __restrict__ adv_out,
                float* __restrict__ tgt_out)
{
    extern __shared__ float sh[];
    float* D = sh;            // TPAD floats: deltas -> advantages
    float* V = sh + TPAD;     // TPAD floats: v_t cache for targets
    __shared__ float wa[NWARP];
    __shared__ float wm[NWARP];
    __shared__ float wcarry[NWARP];

    const int row  = blockIdx.x;
    const int tid  = threadIdx.x;
    const int lane = tid & 31;
    const int wid  = tid >> 5;
    const float* r = rewards + (size_t)row * T_CONST;
    const float* v = values  + (size_t)row * (T_CONST + 1);

    // ── Phase 1: ONE coalesced pass over values + rewards.
    // v[t+1] comes from the next lane via shuffle; lane 31 loads it (L1 hit).
    #pragma unroll 4
    for (int i = 0; i < NITER; ++i) {
        int t = tid + i * THREADS;
        float vt = __ldg(v + t);
        float rt = __ldg(r + t);
        float vt1 = __shfl_down_sync(0xffffffffu, vt, 1);
        if (lane == 31) vt1 = __ldg(v + t + 1);
        int p = padi(t);                    // consecutive t -> conflict-free
        V[p] = vt;
        D[p] = rt + GAMMA * vt1 - vt;
    }
    __syncthreads();

    // ── Phase 2: per-thread local reverse scan of contiguous SEG segment,
    // zero carry -> affine summary (a, m = COEF^SEG).
    const int base = tid * SEG;
    float a = 0.0f;
    #pragma unroll
    for (int k = SEG - 1; k >= 0; --k)
        a = D[padi(base + k)] + COEF * a;

    float m = COEF;                         // COEF^16 via 4 squarings
    m *= m; m *= m; m *= m; m *= m;

    // ── Phase 3a: warp-level REVERSE inclusive scan of affine maps (shuffle).
    #pragma unroll
    for (int d = 1; d < 32; d <<= 1) {
        float a2 = __shfl_down_sync(0xffffffffu, a, d);
        float m2 = __shfl_down_sync(0xffffffffu, m, d);
        if (lane + d < 32) { a = a + m * a2; m = m * m2; }
    }
    if (lane == 0) { wa[wid] = a; wm[wid] = m; }
    __syncthreads();

    // ── Phase 3b: warp 0 scans the 16 warp summaries -> per-warp carries.
    if (wid == 0 && lane < NWARP) {
        float A = wa[lane], M = wm[lane];
        #pragma unroll
        for (int d = 1; d < NWARP; d <<= 1) {
            float A2 = __shfl_down_sync(0x0000ffffu, A, d, NWARP);
            float M2 = __shfl_down_sync(0x0000ffffu, M, d, NWARP);
            if (lane + d < NWARP) { A = A + M * A2; M = M * M2; }
        }
        float c = __shfl_down_sync(0x0000ffffu, A, 1, NWARP);
        wcarry[lane] = (lane == NWARP - 1) ? 0.0f : c;
    }
    __syncthreads();

    // ── Carry entering this thread's segment.
    const float carryW = wcarry[wid];
    float an = __shfl_down_sync(0xffffffffu, a, 1);
    float mn = __shfl_down_sync(0xffffffffu, m, 1);
    const float carry = (lane == 31) ? carryW : an + mn * carryW;

    // ── Phase 4: exact sequential recurrence within segment, seeded w/ carry.
    float acc = carry;
    #pragma unroll
    for (int k = SEG - 1; k >= 0; --k) {
        int p = padi(base + k);
        acc = D[p] + COEF * acc;
        D[p] = acc;                         // delta -> advantage
    }
    __syncthreads();

    // ── Phase 5: all reads from smem (conflict-free), float4 global stores.
    float* arow = adv_out + (size_t)row * T_CONST;
    float* trow = tgt_out + (size_t)row * T_CONST;
    #pragma unroll
    for (int i = 0; i < T_CONST / (4 * THREADS); ++i) {   // 4 iters
        int t = 4 * (tid + i * THREADS);
        int p = padi(t);                    // t%32<=28 -> p..p+3 contiguous
        float a0 = D[p],     a1 = D[p + 1], a2 = D[p + 2], a3 = D[p + 3];
        float v0 = V[p],     v1 = V[p + 1], v2 = V[p + 2], v3 = V[p + 3];
        float4 adv4 = make_float4(a0, a1, a2, a3);
        float4 tgt4 = make_float4(v0 + a0, v1 + a1, v2 + a2, v3 + a3);
        *reinterpret_cast<float4*>(arow + t) = adv4;
        *reinterpret_cast<float4*>(trow + t) = tgt4;
    }
}

extern "C" void kernel_launch(void* const* d_in, const int* in_sizes, int n_in,
                              void* d_out, int out_size)
{
    const float* rewards = (const float*)d_in[0];   // [B, T]
    const float* values  = (const float*)d_in[1];   // [B, T+1]
    float* adv = (float*)d_out;                     // [B, T]
    float* tgt = adv + (size_t)B_CONST * T_CONST;   // [B, T]

    const int smem_bytes = 2 * TPAD * (int)sizeof(float);  // ~66 KB
    cudaFuncSetAttribute(gae_kernel, cudaFuncAttributeMaxDynamicSharedMemorySize, smem_bytes);

    gae_kernel<<<B_CONST, THREADS, smem_bytes>>>(rewards, values, adv, tgt);
}